// round 14
// baseline (speedup 1.0000x reference)
#include <cuda_runtime.h>
#include <stdint.h>

#define SFRAMES 128
#define HW 50176
#define NPTS (SFRAMES*HW)
#define GDIM 48
#define VVOX (GDIM*GDIM*GDIM)   /* 110592 */
#define WORDS (VVOX/32)         /* 3456 */
#define KSEL 16
#define NBUCK 4096
#define CAND_CAP 2048

// Transposed occupancy: occT[w*128 + f] holds bit (v%32) of word w=v/32 for frame f.
__device__ unsigned g_occT[WORDS * SFRAMES];
__device__ float    g_pct[SFRAMES];
__device__ unsigned g_mm[6];   // order-preserving encoded: min x,y,z ; max x,y,z

__device__ __forceinline__ unsigned fenc(float f) {
    unsigned u = __float_as_uint(f);
    return (u & 0x80000000u) ? ~u : (u | 0x80000000u);
}
__device__ __forceinline__ float fdec(unsigned u) {
    u = (u & 0x80000000u) ? (u ^ 0x80000000u) : ~u;
    return __uint_as_float(u);
}

// ---------------------------------------------------------------- init
__global__ void init_kernel() {
    int n = WORDS * SFRAMES;
    for (int i = blockIdx.x * blockDim.x + threadIdx.x; i < n; i += gridDim.x * blockDim.x)
        g_occT[i] = 0u;
    if (blockIdx.x == 0 && threadIdx.x < 6)
        g_mm[threadIdx.x] = (threadIdx.x < 3) ? 0xFFFFFFFFu : 0u;
}

// ---------------------------------------------------------------- per-frame median (50th pct, linear interp)
__global__ void median_kernel(const float* __restrict__ conf) {
    const int f = blockIdx.x;
    const float* c = conf + (size_t)f * HW;
    __shared__ unsigned hist[NBUCK];
    __shared__ float candA[CAND_CAP];
    __shared__ float candB[CAND_CAP];
    __shared__ int nA, nB, sb0, sb1, scb0, scb1;

    for (int i = threadIdx.x; i < NBUCK; i += blockDim.x) hist[i] = 0u;
    if (threadIdx.x == 0) { nA = 0; nB = 0; }
    __syncthreads();

    // pass 1: histogram (bucket = floor(c*4096), exact & monotone since 4096 = 2^12)
    for (int i = threadIdx.x; i < HW; i += blockDim.x) {
        float v = c[i];
        int b = (int)(v * (float)NBUCK);
        b = min(max(b, 0), NBUCK - 1);
        atomicAdd(&hist[b], 1u);
    }
    __syncthreads();

    if (threadIdx.x == 0) {
        const unsigned k0 = (HW - 1) / 2;      // 25087
        const unsigned k1 = k0 + 1;            // 25088
        unsigned cum = 0; int b0 = -1, b1 = -1; unsigned cb0 = 0, cb1 = 0;
        for (int b = 0; b < NBUCK; b++) {
            unsigned h = hist[b];
            if (b0 < 0 && cum + h > k0) { b0 = b; cb0 = cum; }
            if (cum + h > k1) { b1 = b; cb1 = cum; break; }
            cum += h;
        }
        sb0 = b0; sb1 = b1; scb0 = (int)cb0; scb1 = (int)cb1;
    }
    __syncthreads();

    const int b0 = sb0, b1 = sb1;
    // pass 2: gather candidates from the rank buckets
    for (int i = threadIdx.x; i < HW; i += blockDim.x) {
        float v = c[i];
        int b = (int)(v * (float)NBUCK);
        b = min(max(b, 0), NBUCK - 1);
        if (b == b0) { int p = atomicAdd(&nA, 1); if (p < CAND_CAP) candA[p] = v; }
        else if (b == b1) { int p = atomicAdd(&nB, 1); if (p < CAND_CAP) candB[p] = v; }
    }
    __syncthreads();

    if (threadIdx.x == 0) {
        const int k0 = (HW - 1) / 2, k1 = k0 + 1;
        int mA = min(nA, CAND_CAP);
        for (int i = 1; i < mA; i++) {             // insertion sort (~12 elems expected)
            float key = candA[i]; int j = i - 1;
            while (j >= 0 && candA[j] > key) { candA[j + 1] = candA[j]; j--; }
            candA[j + 1] = key;
        }
        float a = candA[k0 - scb0];
        float b;
        if (b1 == b0) {
            b = candA[k1 - scb0];
        } else {
            int mB = min(nB, CAND_CAP);
            for (int i = 1; i < mB; i++) {
                float key = candB[i]; int j = i - 1;
                while (j >= 0 && candB[j] > key) { candB[j + 1] = candB[j]; j--; }
                candB[j + 1] = key;
            }
            b = candB[k1 - scb1];
        }
        g_pct[f] = 0.5f * (a + b);   // == a*0.5 + b*0.5 (halving exact)
    }
}

// ---------------------------------------------------------------- bbox min/max over valid points
__global__ void minmax_kernel(const float* __restrict__ pts, const float* __restrict__ conf) {
    float mnx = 1e38f, mny = 1e38f, mnz = 1e38f;
    float mxx = -1e38f, mxy = -1e38f, mxz = -1e38f;
    const int stride = gridDim.x * blockDim.x;
    for (int i = blockIdx.x * blockDim.x + threadIdx.x; i < NPTS; i += stride) {
        float cv = conf[i];
        float p = g_pct[i / HW];
        if (cv > 0.1f && cv >= p) {
            size_t b = 3 * (size_t)i;
            float x = pts[b], y = pts[b + 1], z = pts[b + 2];
            mnx = fminf(mnx, x); mny = fminf(mny, y); mnz = fminf(mnz, z);
            mxx = fmaxf(mxx, x); mxy = fmaxf(mxy, y); mxz = fmaxf(mxz, z);
        }
    }
#pragma unroll
    for (int o = 16; o; o >>= 1) {
        mnx = fminf(mnx, __shfl_xor_sync(0xffffffffu, mnx, o));
        mny = fminf(mny, __shfl_xor_sync(0xffffffffu, mny, o));
        mnz = fminf(mnz, __shfl_xor_sync(0xffffffffu, mnz, o));
        mxx = fmaxf(mxx, __shfl_xor_sync(0xffffffffu, mxx, o));
        mxy = fmaxf(mxy, __shfl_xor_sync(0xffffffffu, mxy, o));
        mxz = fmaxf(mxz, __shfl_xor_sync(0xffffffffu, mxz, o));
    }
    __shared__ float sm[6][8];
    int w = threadIdx.x >> 5, l = threadIdx.x & 31;
    if (l == 0) { sm[0][w] = mnx; sm[1][w] = mny; sm[2][w] = mnz; sm[3][w] = mxx; sm[4][w] = mxy; sm[5][w] = mxz; }
    __syncthreads();
    if (threadIdx.x == 0) {
        int nw = blockDim.x >> 5;
        float a0 = sm[0][0], a1 = sm[1][0], a2 = sm[2][0];
        float b0 = sm[3][0], b1 = sm[4][0], b2 = sm[5][0];
        for (int j = 1; j < nw; j++) {
            a0 = fminf(a0, sm[0][j]); a1 = fminf(a1, sm[1][j]); a2 = fminf(a2, sm[2][j]);
            b0 = fmaxf(b0, sm[3][j]); b1 = fmaxf(b1, sm[4][j]); b2 = fmaxf(b2, sm[5][j]);
        }
        atomicMin(&g_mm[0], fenc(a0)); atomicMin(&g_mm[1], fenc(a1)); atomicMin(&g_mm[2], fenc(a2));
        atomicMax(&g_mm[3], fenc(b0)); atomicMax(&g_mm[4], fenc(b1)); atomicMax(&g_mm[5], fenc(b2));
    }
}

// ---------------------------------------------------------------- voxelize into transposed bitmaps
__global__ void voxelize_kernel(const float* __restrict__ pts, const float* __restrict__ conf) {
    const float pminx = fdec(g_mm[0]), pminy = fdec(g_mm[1]), pminz = fdec(g_mm[2]);
    const float pmaxx = fdec(g_mm[3]), pmaxy = fdec(g_mm[4]), pmaxz = fdec(g_mm[5]);
    const float vs = fminf(fminf(pmaxx - pminx, pmaxy - pminy), pmaxz - pminz) / 20.0f;
    const int stride = gridDim.x * blockDim.x;
    for (int i = blockIdx.x * blockDim.x + threadIdx.x; i < NPTS; i += stride) {
        float cv = conf[i];
        int f = i / HW;
        float p = g_pct[f];
        if (cv > 0.1f && cv >= p) {
            size_t b = 3 * (size_t)i;
            float x = pts[b], y = pts[b + 1], z = pts[b + 2];
            int ix = (int)floorf((x - pminx) / vs); ix = min(max(ix, 0), GDIM - 1);
            int iy = (int)floorf((y - pminy) / vs); iy = min(max(iy, 0), GDIM - 1);
            int iz = (int)floorf((z - pminz) / vs); iz = min(max(iz, 0), GDIM - 1);
            int vid = (ix * GDIM + iy) * GDIM + iz;
            int w = vid >> 5;
            unsigned bit = 1u << (vid & 31);
            unsigned* addr = &g_occT[(size_t)w * SFRAMES + f];
            // monotone bitmap: a plain-load pre-check is safe (can only skip truly-set bits)
            if ((*addr & bit) == 0u) atomicOr(addr, bit);
        }
    }
}

// ---------------------------------------------------------------- greedy max coverage (single block)
__global__ void __launch_bounds__(1024) greedy_kernel(float* __restrict__ out) {
    __shared__ unsigned cov[WORDS];        // 13824 B
    __shared__ int pg[SFRAMES * 32];       // [frame][chunk] partial gains, 16384 B
    __shared__ int sgain[SFRAMES];
    __shared__ int ssel[SFRAMES];
    __shared__ int sbest;
    __shared__ int stot;

    const int t = threadIdx.x;
    for (int w = t; w < WORDS; w += 1024) cov[w] = 0u;
    if (t < SFRAMES) ssel[t] = 0;
    if (t == 0) stot = 0;
    __syncthreads();

    const int fi = t & 31;        // frame group: frames 4*fi .. 4*fi+3
    const int ch = t >> 5;        // chunk 0..31
    const int WPC = WORDS / 32;   // 108 words per chunk

    for (int it = 0; it < KSEL; ++it) {
        int g0 = 0, g1 = 0, g2 = 0, g3 = 0;
        const int wbase = ch * WPC;
        for (int j = 0; j < WPC; ++j) {
            int w = wbase + j;
            unsigned ncw = ~cov[w];                     // shared broadcast within warp
            const uint4 v = *(const uint4*)&g_occT[(size_t)w * SFRAMES + fi * 4];
            g0 += __popc(v.x & ncw);
            g1 += __popc(v.y & ncw);
            g2 += __popc(v.z & ncw);
            g3 += __popc(v.w & ncw);
        }
        pg[(fi * 4 + 0) * 32 + ch] = g0;
        pg[(fi * 4 + 1) * 32 + ch] = g1;
        pg[(fi * 4 + 2) * 32 + ch] = g2;
        pg[(fi * 4 + 3) * 32 + ch] = g3;
        __syncthreads();

        if (t < SFRAMES) {
            int s = 0;
#pragma unroll
            for (int c2 = 0; c2 < 32; c2++) s += pg[t * 32 + c2];
            sgain[t] = ssel[t] ? -1 : s;
        }
        __syncthreads();

        if (t == 0) {
            int bi = 0, bv = sgain[0];
            for (int f2 = 1; f2 < SFRAMES; f2++)
                if (sgain[f2] > bv) { bv = sgain[f2]; bi = f2; }   // strict > => first max (jnp.argmax)
            sbest = bi;
            ssel[bi] = 1;
            out[it] = (float)bi;
            out[KSEL + it] = (float)bv;
        }
        __syncthreads();

        const int best = sbest;
        for (int w = t; w < WORDS; w += 1024)
            cov[w] |= g_occT[(size_t)w * SFRAMES + best];
        __syncthreads();
    }

    // total coverage = popcount(covered)
    int part = 0;
    for (int w = t; w < WORDS; w += 1024) part += __popc(cov[w]);
#pragma unroll
    for (int o = 16; o; o >>= 1) part += __shfl_xor_sync(0xffffffffu, part, o);
    if ((t & 31) == 0) atomicAdd(&stot, part);
    __syncthreads();
    if (t == 0) out[2 * KSEL] = (float)stot;
}

// ---------------------------------------------------------------- launch
extern "C" void kernel_launch(void* const* d_in, const int* in_sizes, int n_in,
                              void* d_out, int out_size) {
    // inputs: [0]=depth, [1]=depth_conf, [2]=world_points, [3]=world_points_conf, [4]=pose_enc
    const float* wp  = (const float*)d_in[2];
    const float* wpc = (const float*)d_in[3];
    float* out = (float*)d_out;   // [sel(16), scores(16), total_coverage(1)]

    init_kernel<<<432, 1024>>>();
    median_kernel<<<SFRAMES, 256>>>(wpc);
    minmax_kernel<<<1024, 256>>>(wp, wpc);
    voxelize_kernel<<<4096, 256>>>(wp, wpc);
    greedy_kernel<<<1, 1024>>>(out);
}

// round 15
// speedup vs baseline: 1.0061x; 1.0061x over previous
#include <cuda_runtime.h>
#include <stdint.h>

#define SFRAMES 128
#define HW 50176
#define NPTS (SFRAMES*HW)
#define GDIM 48
#define VVOX (GDIM*GDIM*GDIM)   /* 110592 */
#define WORDS (VVOX/32)         /* 3456 */
#define KSEL 16
#define NBUCK 4096
#define CAND_CAP 2048

// Transposed occupancy: occT[w*128 + f] holds bit (v%32) of word w=v/32 for frame f.
__device__ unsigned g_occT[WORDS * SFRAMES];
__device__ float    g_pct[SFRAMES];
__device__ unsigned g_mm[6];   // order-preserving encoded: min x,y,z ; max x,y,z

__device__ __forceinline__ unsigned fenc(float f) {
    unsigned u = __float_as_uint(f);
    return (u & 0x80000000u) ? ~u : (u | 0x80000000u);
}
__device__ __forceinline__ float fdec(unsigned u) {
    u = (u & 0x80000000u) ? (u ^ 0x80000000u) : ~u;
    return __uint_as_float(u);
}

// ---------------------------------------------------------------- init
__global__ void init_kernel() {
    int n = WORDS * SFRAMES;
    for (int i = blockIdx.x * blockDim.x + threadIdx.x; i < n; i += gridDim.x * blockDim.x)
        g_occT[i] = 0u;
    if (blockIdx.x == 0 && threadIdx.x < 6)
        g_mm[threadIdx.x] = (threadIdx.x < 3) ? 0xFFFFFFFFu : 0u;
}

// ---------------------------------------------------------------- per-frame median (50th pct, linear interp)
__global__ void median_kernel(const float* __restrict__ conf) {
    const int f = blockIdx.x;
    const float* c = conf + (size_t)f * HW;
    __shared__ unsigned hist[NBUCK];
    __shared__ float candA[CAND_CAP];
    __shared__ float candB[CAND_CAP];
    __shared__ int nA, nB, sb0, sb1, scb0, scb1;

    for (int i = threadIdx.x; i < NBUCK; i += blockDim.x) hist[i] = 0u;
    if (threadIdx.x == 0) { nA = 0; nB = 0; }
    __syncthreads();

    // pass 1: histogram (bucket = floor(c*4096), exact & monotone since 4096 = 2^12)
    for (int i = threadIdx.x; i < HW; i += blockDim.x) {
        float v = c[i];
        int b = (int)(v * (float)NBUCK);
        b = min(max(b, 0), NBUCK - 1);
        atomicAdd(&hist[b], 1u);
    }
    __syncthreads();

    if (threadIdx.x == 0) {
        const unsigned k0 = (HW - 1) / 2;      // 25087
        const unsigned k1 = k0 + 1;            // 25088
        unsigned cum = 0; int b0 = -1, b1 = -1; unsigned cb0 = 0, cb1 = 0;
        for (int b = 0; b < NBUCK; b++) {
            unsigned h = hist[b];
            if (b0 < 0 && cum + h > k0) { b0 = b; cb0 = cum; }
            if (cum + h > k1) { b1 = b; cb1 = cum; break; }
            cum += h;
        }
        sb0 = b0; sb1 = b1; scb0 = (int)cb0; scb1 = (int)cb1;
    }
    __syncthreads();

    const int b0 = sb0, b1 = sb1;
    // pass 2: gather candidates from the rank buckets
    for (int i = threadIdx.x; i < HW; i += blockDim.x) {
        float v = c[i];
        int b = (int)(v * (float)NBUCK);
        b = min(max(b, 0), NBUCK - 1);
        if (b == b0) { int p = atomicAdd(&nA, 1); if (p < CAND_CAP) candA[p] = v; }
        else if (b == b1) { int p = atomicAdd(&nB, 1); if (p < CAND_CAP) candB[p] = v; }
    }
    __syncthreads();

    if (threadIdx.x == 0) {
        const int k0 = (HW - 1) / 2, k1 = k0 + 1;
        int mA = min(nA, CAND_CAP);
        for (int i = 1; i < mA; i++) {             // insertion sort (~12 elems expected)
            float key = candA[i]; int j = i - 1;
            while (j >= 0 && candA[j] > key) { candA[j + 1] = candA[j]; j--; }
            candA[j + 1] = key;
        }
        float a = candA[k0 - scb0];
        float b;
        if (b1 == b0) {
            b = candA[k1 - scb0];
        } else {
            int mB = min(nB, CAND_CAP);
            for (int i = 1; i < mB; i++) {
                float key = candB[i]; int j = i - 1;
                while (j >= 0 && candB[j] > key) { candB[j + 1] = candB[j]; j--; }
                candB[j + 1] = key;
            }
            b = candB[k1 - scb1];
        }
        g_pct[f] = 0.5f * (a + b);   // == a*0.5 + b*0.5 (halving exact)
    }
}

// ---------------------------------------------------------------- bbox min/max over valid points
__global__ void minmax_kernel(const float* __restrict__ pts, const float* __restrict__ conf) {
    float mnx = 1e38f, mny = 1e38f, mnz = 1e38f;
    float mxx = -1e38f, mxy = -1e38f, mxz = -1e38f;
    const int stride = gridDim.x * blockDim.x;
    for (int i = blockIdx.x * blockDim.x + threadIdx.x; i < NPTS; i += stride) {
        float cv = conf[i];
        float p = g_pct[i / HW];
        if (cv > 0.1f && cv >= p) {
            size_t b = 3 * (size_t)i;
            float x = pts[b], y = pts[b + 1], z = pts[b + 2];
            mnx = fminf(mnx, x); mny = fminf(mny, y); mnz = fminf(mnz, z);
            mxx = fmaxf(mxx, x); mxy = fmaxf(mxy, y); mxz = fmaxf(mxz, z);
        }
    }
#pragma unroll
    for (int o = 16; o; o >>= 1) {
        mnx = fminf(mnx, __shfl_xor_sync(0xffffffffu, mnx, o));
        mny = fminf(mny, __shfl_xor_sync(0xffffffffu, mny, o));
        mnz = fminf(mnz, __shfl_xor_sync(0xffffffffu, mnz, o));
        mxx = fmaxf(mxx, __shfl_xor_sync(0xffffffffu, mxx, o));
        mxy = fmaxf(mxy, __shfl_xor_sync(0xffffffffu, mxy, o));
        mxz = fmaxf(mxz, __shfl_xor_sync(0xffffffffu, mxz, o));
    }
    __shared__ float sm[6][8];
    int w = threadIdx.x >> 5, l = threadIdx.x & 31;
    if (l == 0) { sm[0][w] = mnx; sm[1][w] = mny; sm[2][w] = mnz; sm[3][w] = mxx; sm[4][w] = mxy; sm[5][w] = mxz; }
    __syncthreads();
    if (threadIdx.x == 0) {
        int nw = blockDim.x >> 5;
        float a0 = sm[0][0], a1 = sm[1][0], a2 = sm[2][0];
        float b0 = sm[3][0], b1 = sm[4][0], b2 = sm[5][0];
        for (int j = 1; j < nw; j++) {
            a0 = fminf(a0, sm[0][j]); a1 = fminf(a1, sm[1][j]); a2 = fminf(a2, sm[2][j]);
            b0 = fmaxf(b0, sm[3][j]); b1 = fmaxf(b1, sm[4][j]); b2 = fmaxf(b2, sm[5][j]);
        }
        atomicMin(&g_mm[0], fenc(a0)); atomicMin(&g_mm[1], fenc(a1)); atomicMin(&g_mm[2], fenc(a2));
        atomicMax(&g_mm[3], fenc(b0)); atomicMax(&g_mm[4], fenc(b1)); atomicMax(&g_mm[5], fenc(b2));
    }
}

// ---------------------------------------------------------------- voxelize into transposed bitmaps
__global__ void voxelize_kernel(const float* __restrict__ pts, const float* __restrict__ conf) {
    const float pminx = fdec(g_mm[0]), pminy = fdec(g_mm[1]), pminz = fdec(g_mm[2]);
    const float pmaxx = fdec(g_mm[3]), pmaxy = fdec(g_mm[4]), pmaxz = fdec(g_mm[5]);
    const float vs = fminf(fminf(pmaxx - pminx, pmaxy - pminy), pmaxz - pminz) / 20.0f;
    const int stride = gridDim.x * blockDim.x;
    for (int i = blockIdx.x * blockDim.x + threadIdx.x; i < NPTS; i += stride) {
        float cv = conf[i];
        int f = i / HW;
        float p = g_pct[f];
        if (cv > 0.1f && cv >= p) {
            size_t b = 3 * (size_t)i;
            float x = pts[b], y = pts[b + 1], z = pts[b + 2];
            int ix = (int)floorf((x - pminx) / vs); ix = min(max(ix, 0), GDIM - 1);
            int iy = (int)floorf((y - pminy) / vs); iy = min(max(iy, 0), GDIM - 1);
            int iz = (int)floorf((z - pminz) / vs); iz = min(max(iz, 0), GDIM - 1);
            int vid = (ix * GDIM + iy) * GDIM + iz;
            int w = vid >> 5;
            unsigned bit = 1u << (vid & 31);
            unsigned* addr = &g_occT[(size_t)w * SFRAMES + f];
            // monotone bitmap: a plain-load pre-check is safe (can only skip truly-set bits)
            if ((*addr & bit) == 0u) atomicOr(addr, bit);
        }
    }
}

// ---------------------------------------------------------------- greedy max coverage (single block)
__global__ void __launch_bounds__(1024) greedy_kernel(float* __restrict__ out) {
    __shared__ unsigned cov[WORDS];        // 13824 B
    __shared__ int pg[SFRAMES * 32];       // [frame][chunk] partial gains, 16384 B
    __shared__ int sgain[SFRAMES];
    __shared__ int ssel[SFRAMES];
    __shared__ int sbest;
    __shared__ int stot;

    const int t = threadIdx.x;
    for (int w = t; w < WORDS; w += 1024) cov[w] = 0u;
    if (t < SFRAMES) ssel[t] = 0;
    if (t == 0) stot = 0;
    __syncthreads();

    const int fi = t & 31;        // frame group: frames 4*fi .. 4*fi+3
    const int ch = t >> 5;        // chunk 0..31
    const int WPC = WORDS / 32;   // 108 words per chunk

    for (int it = 0; it < KSEL; ++it) {
        int g0 = 0, g1 = 0, g2 = 0, g3 = 0;
        const int wbase = ch * WPC;
        for (int j = 0; j < WPC; ++j) {
            int w = wbase + j;
            unsigned ncw = ~cov[w];                     // shared broadcast within warp
            const uint4 v = *(const uint4*)&g_occT[(size_t)w * SFRAMES + fi * 4];
            g0 += __popc(v.x & ncw);
            g1 += __popc(v.y & ncw);
            g2 += __popc(v.z & ncw);
            g3 += __popc(v.w & ncw);
        }
        pg[(fi * 4 + 0) * 32 + ch] = g0;
        pg[(fi * 4 + 1) * 32 + ch] = g1;
        pg[(fi * 4 + 2) * 32 + ch] = g2;
        pg[(fi * 4 + 3) * 32 + ch] = g3;
        __syncthreads();

        if (t < SFRAMES) {
            int s = 0;
#pragma unroll
            for (int c2 = 0; c2 < 32; c2++) s += pg[t * 32 + c2];
            sgain[t] = ssel[t] ? -1 : s;
        }
        __syncthreads();

        if (t == 0) {
            int bi = 0, bv = sgain[0];
            for (int f2 = 1; f2 < SFRAMES; f2++)
                if (sgain[f2] > bv) { bv = sgain[f2]; bi = f2; }   // strict > => first max (jnp.argmax)
            sbest = bi;
            ssel[bi] = 1;
            out[it] = (float)bi;
            out[KSEL + it] = (float)bv;
        }
        __syncthreads();

        const int best = sbest;
        for (int w = t; w < WORDS; w += 1024)
            cov[w] |= g_occT[(size_t)w * SFRAMES + best];
        __syncthreads();
    }

    // total coverage = popcount(covered)
    int part = 0;
    for (int w = t; w < WORDS; w += 1024) part += __popc(cov[w]);
#pragma unroll
    for (int o = 16; o; o >>= 1) part += __shfl_xor_sync(0xffffffffu, part, o);
    if ((t & 31) == 0) atomicAdd(&stot, part);
    __syncthreads();
    if (t == 0) out[2 * KSEL] = (float)stot;
}

// ---------------------------------------------------------------- launch
extern "C" void kernel_launch(void* const* d_in, const int* in_sizes, int n_in,
                              void* d_out, int out_size) {
    // inputs: [0]=depth, [1]=depth_conf, [2]=world_points, [3]=world_points_conf, [4]=pose_enc
    const float* wp  = (const float*)d_in[2];
    const float* wpc = (const float*)d_in[3];
    float* out = (float*)d_out;   // [sel(16), scores(16), total_coverage(1)]

    init_kernel<<<432, 1024>>>();
    median_kernel<<<SFRAMES, 256>>>(wpc);
    minmax_kernel<<<1024, 256>>>(wp, wpc);
    voxelize_kernel<<<4096, 256>>>(wp, wpc);
    greedy_kernel<<<1, 1024>>>(out);
}